// round 15
// baseline (speedup 1.0000x reference)
#include <cuda_runtime.h>
#include <math.h>

// WeightedGaussianPool: O[i,b] = sum_j cos(pi/2*d_ij)*step(1-d_ij)*f_j
//                                      * exp(-beta*(d_ij-means[b])^2)
// N=2048, B=64, beta=4096, means=linspace(0,1,64).
//
// R15 = R14 (single launch, 128-wide chunks, unroll-1 producer groups) +
// SOFTWARE-PIPELINED producer: group g+1's 4 loads (x,y,z,f) are issued
// before group g is processed. Max in-flight LDGs ~8 (R10-proven safe for
// the cross-CTA L1tex queue; R12's 16 front-batched stride-3 LDGs cost +50%)
// while group compute hides the next batch's load latency (R14's exposure).
//  - 128-wide j-chunks, group-compacted into one ping-pong pair list,
//    one sync/pad/consumer pass per visit.
//  - consumer: software-pipelined LDS.128 walk, 4 accumulators, single
//    predicate-routed EX2 per pair (lane l owns bases l and l+32; 32/63
//    apart so at most one tap nonzero -> exact).
//  - block == row i (grid 2048, 128 thr), block smem reduction, plain STG.

#define CUTOFF   5.0f
#define PI_HALF  1.5707963267948966f
#define NBASIS   64
#define WPB      4

__device__ __forceinline__ float ex2_fast(float x) {
    float r;
    asm("ex2.approx.ftz.f32 %0, %1;" : "=f"(r) : "f"(x));
    return r;
}
__device__ __forceinline__ float sqrt_fast(float x) {
    float r;
    asm("sqrt.approx.ftz.f32 %0, %1;" : "=f"(r) : "f"(x));
    return r;
}

__global__ __launch_bounds__(WPB * 32, 16)
void wgp_main_kernel(const float* __restrict__ f,
                     const float* __restrict__ coords,
                     const float* __restrict__ means,
                     const float* __restrict__ beta_p,
                     float* __restrict__ out,
                     int N) {
    // ping-pong pair list: 128 pairs + 3 pad + prefetch over-read headroom
    __shared__ __align__(16) float2 buf[WPB][2][140];
    __shared__ float red[WPB][NBASIS];

    const int lane = threadIdx.x & 31;
    const int wrp  = threadIdx.x >> 5;
    const int i    = blockIdx.x;                 // row

    const float beta = *beta_p;
    const float a    = sqrtf(beta * 1.4426950408889634f); // sqrt(beta*log2 e)
    const float aC   = a / CUTOFF;                         // raw-dist scale
    const float pC   = PI_HALF / CUTOFF;
    const float C2   = CUTOFF * CUTOFF;
    const float am1  = a * means[lane];
    const float am2  = a * means[lane + 32];
    const float D    = am2 - am1;                // warp-uniform
    const float midp = 0.5f * (am1 + am2);

    const float xi = coords[3 * i + 0];
    const float yi = coords[3 * i + 1];
    const float zi = coords[3 * i + 2];

    float acc1a = 0.0f, acc2a = 0.0f;
    float acc1b = 0.0f, acc2b = 0.0f;
    int pb = 0;

    const unsigned below = (1u << lane) - 1u;
    const int nch128 = (N + 127) >> 7;           // 128-wide chunks

    for (int c = wrp; c < nch128; c += WPB) {
        float2* bp = buf[wrp][pb];
        int base = 0;

        // ---- software-pipelined producer: prefetch group g+1, process g ----
        int j = (c << 7) + lane;
        float nx = coords[3 * j + 0];
        float ny = coords[3 * j + 1];
        float nz = coords[3 * j + 2];
        float nf = f[j];

        #pragma unroll 1   // keep in-flight LDG batches bounded (L1tex queue)
        for (int g = 0; g < 4; ++g) {
            const float cx = nx, cy = ny, cz = nz, fv = nf;
            if (g < 3) {
                const int jn = j + 32;
                nx = coords[3 * jn + 0];
                ny = coords[3 * jn + 1];
                nz = coords[3 * jn + 2];
                nf = f[jn];
            }

            const float dx = xi - cx;
            const float dy = yi - cy;
            const float dz = zi - cz;
            const float sq = fmaf(dx, dx, fmaf(dy, dy, dz * dz));
            const bool act = (sq <= C2) && (j < N);
            float dp = 0.0f, w = 0.0f;
            if (act) {
                const float dr = sqrt_fast(sq);
                dp = aC * dr;
                w  = __cosf(pC * dr) * fv;
            }
            const unsigned b = __ballot_sync(0xffffffffu, act);
            if (act) bp[base + __popc(b & below)] = make_float2(dp, w);
            base += __popc(b);
            j += 32;
        }

        const int nact = base;
        if (!nact) continue;

        if (lane < 3) bp[nact + lane] = make_float2(1.0e4f, 0.0f);  // pad x4
        __syncwarp();

        const int n4 = (nact + 3) & ~3;

#define PAIR(dq, wq, A1, A2)                                      \
        {                                                         \
            const float t1 = (dq) - am1;                          \
            const bool  lo = (dq) < midp;                         \
            const float t  = lo ? t1 : (t1 - D);                  \
            const float e  = ex2_fast(-t * t);                    \
            if (lo) A1 = fmaf((wq), e, A1);                       \
            else    A2 = fmaf((wq), e, A2);                       \
        }

        // software-pipelined: prefetch quad k+4 while computing k
        float4 q0 = *(const float4*)&bp[0];
        float4 q1 = *(const float4*)&bp[2];
        for (int k = 0; k < n4; k += 4) {
            const float4 p0 = q0;
            const float4 p1 = q1;
            q0 = *(const float4*)&bp[k + 4];   // over-read in-bounds, unused past end
            q1 = *(const float4*)&bp[k + 6];
            PAIR(p0.x, p0.y, acc1a, acc2a)
            PAIR(p0.z, p0.w, acc1b, acc2b)
            PAIR(p1.x, p1.y, acc1a, acc2a)
            PAIR(p1.z, p1.w, acc1b, acc2b)
        }
#undef PAIR
        pb ^= 1;   // next visit writes the other buffer (no trailing sync)
    }

    // block reduction across WPB partitions, one STG per element
    red[wrp][lane]      = acc1a + acc1b;
    red[wrp][lane + 32] = acc2a + acc2b;
    __syncthreads();

    const int tid = threadIdx.x;
    if (tid < NBASIS) {
        float s = 0.0f;
        #pragma unroll
        for (int r = 0; r < WPB; ++r) s += red[r][tid];
        out[i * NBASIS + tid] = s;
    }
}

extern "C" void kernel_launch(void* const* d_in, const int* in_sizes, int n_in,
                              void* d_out, int out_size) {
    const float* f      = (const float*)d_in[0];
    const float* coords = (const float*)d_in[1];
    const float* means  = (const float*)d_in[2];
    const float* beta   = (const float*)d_in[3];
    float* out          = (float*)d_out;

    const int N = in_sizes[0];   // 2048

    wgp_main_kernel<<<N, WPB * 32>>>(f, coords, means, beta, out, N);
}

// round 16
// speedup vs baseline: 1.0012x; 1.0012x over previous
#include <cuda_runtime.h>
#include <math.h>

// WeightedGaussianPool: O[i,b] = sum_j cos(pi/2*d_ij)*step(1-d_ij)*f_j
//                                      * exp(-beta*(d_ij-means[b])^2)
// N=2048, B=64, beta=4096, means=linspace(0,1,64).
//
// R16 = R11's main loop (best kernel: 21.6us; packed float4 producer,
// 128-wide chunks, group compaction, pipelined LDS.128 consumer, single
// predicate-routed EX2 per pair) fused into ONE launch:
//  - first ceil(N/128) CTAs pack (x,y,z,f) -> g_pk, then signal via
//    atomic counter + flag; all CTAs spin-wait (1 thread, nanosleep).
//  - SAFE: __launch_bounds__(128,16) pins regs<=32 -> 16 CTAs/SM ->
//    capacity 2368 >= grid 2048, all CTAs co-resident, no deadlock.
//  - last-finishing CTA resets the barrier state -> replay-deterministic.
// This removes R11's 1.66us prep-kernel + launch gap (R12-R15 proved the
// packed producer cannot be replaced by AoS loads at any schedule).

#define CUTOFF   5.0f
#define PI_HALF  1.5707963267948966f
#define NBASIS   64
#define WPB      4
#define NMAX     4096

__device__ float4 g_pk[NMAX];
__device__ unsigned int g_arr  = 0;
__device__ unsigned int g_done = 0;
__device__ volatile unsigned int g_flag = 0;

__device__ __forceinline__ float ex2_fast(float x) {
    float r;
    asm("ex2.approx.ftz.f32 %0, %1;" : "=f"(r) : "f"(x));
    return r;
}
__device__ __forceinline__ float sqrt_fast(float x) {
    float r;
    asm("sqrt.approx.ftz.f32 %0, %1;" : "=f"(r) : "f"(x));
    return r;
}

__global__ __launch_bounds__(WPB * 32, 16)
void wgp_main_kernel(const float* __restrict__ f,
                     const float* __restrict__ coords,
                     const float* __restrict__ means,
                     const float* __restrict__ beta_p,
                     float* __restrict__ out,
                     int N) {
    // ping-pong pair list: 128 pairs + 3 pad + prefetch over-read headroom
    __shared__ __align__(16) float2 buf[WPB][2][140];
    __shared__ float red[WPB][NBASIS];

    const int lane = threadIdx.x & 31;
    const int wrp  = threadIdx.x >> 5;
    const int i    = blockIdx.x;                 // row

    // ---- phase 1: distributed pack + device barrier ----
    const int npack = (N + 127) >> 7;            // 128 points per packer CTA
    if (blockIdx.x < npack) {
        const int p = (blockIdx.x << 7) + threadIdx.x;
        if (p < N)
            g_pk[p] = make_float4(coords[3 * p + 0], coords[3 * p + 1],
                                  coords[3 * p + 2], f[p]);
        __threadfence();
        __syncthreads();                         // CTA's 128 stores done
        if (threadIdx.x == 0) {
            const unsigned r = atomicAdd(&g_arr, 1u);
            if (r == (unsigned)(npack - 1)) {
                __threadfence();
                g_flag = 1;                      // release
            }
        }
    }
    if (threadIdx.x == 0) {
        while (g_flag == 0u) __nanosleep(64);
        __threadfence();                         // acquire
    }
    __syncthreads();

    // ---- phase 2: R11 main loop (unchanged) ----
    const float beta = *beta_p;
    const float a    = sqrtf(beta * 1.4426950408889634f); // sqrt(beta*log2 e)
    const float aC   = a / CUTOFF;                         // raw-dist scale
    const float pC   = PI_HALF / CUTOFF;
    const float C2   = CUTOFF * CUTOFF;
    const float am1  = a * means[lane];
    const float am2  = a * means[lane + 32];
    const float D    = am2 - am1;                // warp-uniform
    const float midp = 0.5f * (am1 + am2);

    const float4 pi4 = g_pk[i];
    const float xi = pi4.x, yi = pi4.y, zi = pi4.z;

    float acc1a = 0.0f, acc2a = 0.0f;
    float acc1b = 0.0f, acc2b = 0.0f;
    int pb = 0;

    const unsigned below = (1u << lane) - 1u;
    const int nch128 = (N + 127) >> 7;           // 128-wide chunks

    for (int c = wrp; c < nch128; c += WPB) {
        float2* bp = buf[wrp][pb];
        int base = 0;

        #pragma unroll
        for (int g = 0; g < 4; ++g) {
            const int j = (c << 7) + (g << 5) + lane;
            const float4 p = g_pk[j];
            const float dx = xi - p.x;
            const float dy = yi - p.y;
            const float dz = zi - p.z;
            const float sq = fmaf(dx, dx, fmaf(dy, dy, dz * dz));
            const bool act = (sq <= C2) && (j < N);
            float dp = 0.0f, w = 0.0f;
            if (act) {
                const float dr = sqrt_fast(sq);
                dp = aC * dr;
                w  = __cosf(pC * dr) * p.w;
            }
            const unsigned b = __ballot_sync(0xffffffffu, act);
            if (act) bp[base + __popc(b & below)] = make_float2(dp, w);
            base += __popc(b);
        }

        const int nact = base;
        if (!nact) continue;

        if (lane < 3) bp[nact + lane] = make_float2(1.0e4f, 0.0f);  // pad x4
        __syncwarp();

        const int n4 = (nact + 3) & ~3;

#define PAIR(dq, wq, A1, A2)                                      \
        {                                                         \
            const float t1 = (dq) - am1;                          \
            const bool  lo = (dq) < midp;                         \
            const float t  = lo ? t1 : (t1 - D);                  \
            const float e  = ex2_fast(-t * t);                    \
            if (lo) A1 = fmaf((wq), e, A1);                       \
            else    A2 = fmaf((wq), e, A2);                       \
        }

        // software-pipelined: prefetch quad k+4 while computing k
        float4 q0 = *(const float4*)&bp[0];
        float4 q1 = *(const float4*)&bp[2];
        for (int k = 0; k < n4; k += 4) {
            const float4 p0 = q0;
            const float4 p1 = q1;
            q0 = *(const float4*)&bp[k + 4];   // over-read in-bounds, unused past end
            q1 = *(const float4*)&bp[k + 6];
            PAIR(p0.x, p0.y, acc1a, acc2a)
            PAIR(p0.z, p0.w, acc1b, acc2b)
            PAIR(p1.x, p1.y, acc1a, acc2a)
            PAIR(p1.z, p1.w, acc1b, acc2b)
        }
#undef PAIR
        pb ^= 1;   // next visit writes the other buffer (no trailing sync)
    }

    // block reduction across WPB partitions, one STG per element
    red[wrp][lane]      = acc1a + acc1b;
    red[wrp][lane + 32] = acc2a + acc2b;
    __syncthreads();

    const int tid = threadIdx.x;
    if (tid < NBASIS) {
        float s = 0.0f;
        #pragma unroll
        for (int r = 0; r < WPB; ++r) s += red[r][tid];
        out[i * NBASIS + tid] = s;
    }

    // ---- phase 3: barrier state reset (replay determinism) ----
    __syncthreads();
    if (threadIdx.x == 0) {
        const unsigned r = atomicAdd(&g_done, 1u);
        if (r == (unsigned)(gridDim.x - 1)) {    // last CTA: all passed barrier
            g_arr  = 0;
            g_done = 0;
            g_flag = 0;
        }
    }
}

extern "C" void kernel_launch(void* const* d_in, const int* in_sizes, int n_in,
                              void* d_out, int out_size) {
    const float* f      = (const float*)d_in[0];
    const float* coords = (const float*)d_in[1];
    const float* means  = (const float*)d_in[2];
    const float* beta   = (const float*)d_in[3];
    float* out          = (float*)d_out;

    const int N = in_sizes[0];   // 2048

    wgp_main_kernel<<<N, WPB * 32>>>(f, coords, means, beta, out, N);
}

// round 17
// speedup vs baseline: 1.1413x; 1.1400x over previous
#include <cuda_runtime.h>
#include <math.h>

// WeightedGaussianPool: O[i,b] = sum_j cos(pi/2*d_ij)*step(1-d_ij)*f_j
//                                      * exp(-beta*(d_ij-means[b])^2)
// N=2048, B=64, beta=4096, means=linspace(0,1,64).
//
// R17: warp-local smem transpose producer (R11's vectorized loads + 128-wide
// amortization, single launch, no global pack / no device barrier):
//  - per 128-pt chunk: 3 coalesced LDG.128 stage raw coords into smem
//    (+4 coalesced LDG.32 for f), one syncwarp, then stride-3 LDS reads
//    (gcd(3,32)=1 -> conflict-free permutation).
//  - 128-wide j-chunks, group-compacted pair list, one pad/sync/consumer
//    pass per visit.
//  - consumer: software-pipelined LDS.128 walk, 4 accumulators, single
//    predicate-routed EX2 per pair (lane l owns bases l and l+32; 32/63
//    apart so at most one tap nonzero -> exact).
//  - block == row i (grid 2048, 128 thr, launch_bounds(128,14): single wave),
//    block smem reduction, plain STG.

#define CUTOFF   5.0f
#define PI_HALF  1.5707963267948966f
#define NBASIS   64
#define WPB      4

__device__ __forceinline__ float ex2_fast(float x) {
    float r;
    asm("ex2.approx.ftz.f32 %0, %1;" : "=f"(r) : "f"(x));
    return r;
}
__device__ __forceinline__ float sqrt_fast(float x) {
    float r;
    asm("sqrt.approx.ftz.f32 %0, %1;" : "=f"(r) : "f"(x));
    return r;
}

__global__ __launch_bounds__(WPB * 32, 14)
void wgp_main_kernel(const float* __restrict__ f,
                     const float* __restrict__ coords,
                     const float* __restrict__ means,
                     const float* __restrict__ beta_p,
                     float* __restrict__ out,
                     int N) {
    __shared__ __align__(16) float  stage[WPB][384];   // raw coords of a 128-pt chunk
    __shared__ __align__(16) float2 buf[WPB][140];     // compacted pair list
    __shared__ float red[WPB][NBASIS];

    const int lane = threadIdx.x & 31;
    const int wrp  = threadIdx.x >> 5;
    const int i    = blockIdx.x;                 // row

    const float beta = *beta_p;
    const float a    = sqrtf(beta * 1.4426950408889634f); // sqrt(beta*log2 e)
    const float aC   = a / CUTOFF;                         // raw-dist scale
    const float pC   = PI_HALF / CUTOFF;
    const float C2   = CUTOFF * CUTOFF;
    const float am1  = a * means[lane];
    const float am2  = a * means[lane + 32];
    const float D    = am2 - am1;                // warp-uniform
    const float midp = 0.5f * (am1 + am2);

    const float xi = coords[3 * i + 0];
    const float yi = coords[3 * i + 1];
    const float zi = coords[3 * i + 2];

    float acc1a = 0.0f, acc2a = 0.0f;
    float acc1b = 0.0f, acc2b = 0.0f;

    const unsigned below = (1u << lane) - 1u;
    const int nch128 = (N + 127) >> 7;           // 128-wide chunks

    for (int c = wrp; c < nch128; c += WPB) {
        float2* bp = buf[wrp];
        float*  st = stage[wrp];

        // ---- stage: 3 coalesced LDG.128 -> STS.128 (384 floats = 128 pts) ----
        {
            const float4* cb = (const float4*)(coords + (size_t)c * 384);
            float4* sv = (float4*)st;
            sv[lane]      = cb[lane];
            sv[lane + 32] = cb[lane + 32];
            sv[lane + 64] = cb[lane + 64];
        }
        // f: 4 coalesced LDG.32, kept in registers
        const int jc = c << 7;
        float fr0 = f[jc + lane];
        float fr1 = f[jc + 32 + lane];
        float fr2 = f[jc + 64 + lane];
        float fr3 = f[jc + 96 + lane];
        __syncwarp();

        int base = 0;
        #pragma unroll
        for (int g = 0; g < 4; ++g) {
            const float fv = (g == 0) ? fr0 : (g == 1) ? fr1 : (g == 2) ? fr2 : fr3;
            const float cx = st[g * 96 + 3 * lane + 0];   // stride-3: conflict-free
            const float cy = st[g * 96 + 3 * lane + 1];
            const float cz = st[g * 96 + 3 * lane + 2];
            const int   j  = jc + (g << 5) + lane;

            const float dx = xi - cx;
            const float dy = yi - cy;
            const float dz = zi - cz;
            const float sq = fmaf(dx, dx, fmaf(dy, dy, dz * dz));
            const bool act = (sq <= C2) && (j < N);
            float dp = 0.0f, w = 0.0f;
            if (act) {
                const float dr = sqrt_fast(sq);
                dp = aC * dr;
                w  = __cosf(pC * dr) * fv;
            }
            const unsigned b = __ballot_sync(0xffffffffu, act);
            if (act) bp[base + __popc(b & below)] = make_float2(dp, w);
            base += __popc(b);
        }

        const int nact = base;
        if (nact) {
            if (lane < 3) bp[nact + lane] = make_float2(1.0e4f, 0.0f);  // pad x4
            __syncwarp();

            const int n4 = (nact + 3) & ~3;

#define PAIR(dq, wq, A1, A2)                                      \
            {                                                     \
                const float t1 = (dq) - am1;                      \
                const bool  lo = (dq) < midp;                     \
                const float t  = lo ? t1 : (t1 - D);              \
                const float e  = ex2_fast(-t * t);                \
                if (lo) A1 = fmaf((wq), e, A1);                   \
                else    A2 = fmaf((wq), e, A2);                   \
            }

            // software-pipelined: prefetch quad k+4 while computing k
            float4 q0 = *(const float4*)&bp[0];
            float4 q1 = *(const float4*)&bp[2];
            for (int k = 0; k < n4; k += 4) {
                const float4 p0 = q0;
                const float4 p1 = q1;
                q0 = *(const float4*)&bp[k + 4];  // over-read in-bounds, unused
                q1 = *(const float4*)&bp[k + 6];
                PAIR(p0.x, p0.y, acc1a, acc2a)
                PAIR(p0.z, p0.w, acc1b, acc2b)
                PAIR(p1.x, p1.y, acc1a, acc2a)
                PAIR(p1.z, p1.w, acc1b, acc2b)
            }
#undef PAIR
        }
        __syncwarp();   // WAR guard: bp + stage reuse next visit
    }

    // block reduction across WPB partitions, one STG per element
    red[wrp][lane]      = acc1a + acc1b;
    red[wrp][lane + 32] = acc2a + acc2b;
    __syncthreads();

    const int tid = threadIdx.x;
    if (tid < NBASIS) {
        float s = 0.0f;
        #pragma unroll
        for (int r = 0; r < WPB; ++r) s += red[r][tid];
        out[i * NBASIS + tid] = s;
    }
}

extern "C" void kernel_launch(void* const* d_in, const int* in_sizes, int n_in,
                              void* d_out, int out_size) {
    const float* f      = (const float*)d_in[0];
    const float* coords = (const float*)d_in[1];
    const float* means  = (const float*)d_in[2];
    const float* beta   = (const float*)d_in[3];
    float* out          = (float*)d_out;

    const int N = in_sizes[0];   // 2048

    wgp_main_kernel<<<N, WPB * 32>>>(f, coords, means, beta, out, N);
}